// round 8
// baseline (speedup 1.0000x reference)
#include <cuda_runtime.h>
#include <cuda_fp16.h>
#include <cstdint>

// QuantumLinear == x @ W_real^T + bias  (magnitude*cos(atan2(i,r)) == r identically;
// weight_imag is dead code).
//
// Round 8: fp16 m16n8k16 single pass (minimum instruction count on the
// per-instruction-paced fallback HMMA path). Edge work: fused prep kernel
// (1 launch), BK=64 / 3-stage (half the barriers, more ldsm prefetch room).

#define M_DIM 8192
#define N_DIM 4096
#define K_DIM 4096

#define BM 128
#define BN 128
#define BK 64                       // fp16 elements per K-tile (128B rows)
#define STAGES 3
#define KTILES (K_DIM / BK)         // 64

// smem rows: 128B data + 16B pad = 144B stride -> conflict-free ldmatrix
#define ROW_STRIDE 144
#define TILE_BYTES (128 * ROW_STRIDE)          // 18432
#define STAGE_BYTES (2 * TILE_BYTES)           // 36864
#define SMEM_TOTAL (STAGES * STAGE_BYTES)      // 110592 (x2 CTAs = 221KB/SM)

// ---------------- scratch: fp16 copies ----------------
__device__ __half g_xh[(size_t)M_DIM * K_DIM];
__device__ __half g_wh[(size_t)N_DIM * K_DIM];

// ---------------- helpers ----------------
__device__ __forceinline__ uint32_t smem_u32(const void* p) {
    uint32_t a;
    asm("{ .reg .u64 t; cvta.to.shared.u64 t, %1; cvt.u32.u64 %0, t; }" : "=r"(a) : "l"(p));
    return a;
}

__device__ __forceinline__ void cp16(uint32_t dst, const void* src) {
    asm volatile("cp.async.cg.shared.global [%0], [%1], 16;" :: "r"(dst), "l"(src));
}
#define CP_COMMIT() asm volatile("cp.async.commit_group;" ::: "memory")
#define CP_WAIT(n)  asm volatile("cp.async.wait_group %0;" :: "n"(n) : "memory")

__device__ __forceinline__ void ldsm4(uint32_t* r, uint32_t addr) {
    asm volatile("ldmatrix.sync.aligned.m8n8.x4.shared.b16 {%0,%1,%2,%3}, [%4];"
                 : "=r"(r[0]), "=r"(r[1]), "=r"(r[2]), "=r"(r[3]) : "r"(addr));
}

__device__ __forceinline__ void mma16816(float* d, const uint32_t* a,
                                         uint32_t b0, uint32_t b1) {
    asm volatile(
        "mma.sync.aligned.m16n8k16.row.col.f32.f16.f16.f32 "
        "{%0,%1,%2,%3}, {%4,%5,%6,%7}, {%8,%9}, {%0,%1,%2,%3};"
        : "+f"(d[0]), "+f"(d[1]), "+f"(d[2]), "+f"(d[3])
        : "r"(a[0]), "r"(a[1]), "r"(a[2]), "r"(a[3]), "r"(b0), "r"(b1));
}

// ---------------- prep: fused fp32 -> fp16 (rn) for X then W ----------------
#define N4X (M_DIM * K_DIM / 4)    // 8388608
#define N4W (N_DIM * K_DIM / 4)    // 4194304

__global__ __launch_bounds__(256)
void to_fp16_fused(const float4* __restrict__ xs, __half2* __restrict__ xd,
                   const float4* __restrict__ ws, __half2* __restrict__ wd)
{
    int i = blockIdx.x * blockDim.x + threadIdx.x;
    const float4* s;
    __half2* d;
    if (i < N4X) { s = xs + i; d = xd + 2 * (size_t)i; }
    else         { int j = i - N4X; s = ws + j; d = wd + 2 * (size_t)j; }
    float4 v = *s;
    d[0] = __floats2half2_rn(v.x, v.y);
    d[1] = __floats2half2_rn(v.z, v.w);
}

// ---------------- GEMM ----------------
__global__ __launch_bounds__(256, 2)
void qgemm_fp16(const __half* __restrict__ X,   // [M, K] fp16
                const __half* __restrict__ W,   // [N, K] fp16
                const float* __restrict__ bias, // [N]
                float* __restrict__ out)        // [M, N]
{
    extern __shared__ char smem[];
    const uint32_t sb = smem_u32(smem);

    const int tid  = threadIdx.x;
    const int wid  = tid >> 5;
    const int lane = tid & 31;
    const int warpM = wid & 3;      // m offset 32*warpM
    const int warpN = wid >> 2;     // n offset 64*warpN

    // ---- grouped rasterization: 8 m-tiles per group column ----
    const int pid = blockIdx.x;
    const int group_id = pid >> 8;
    const int pid_m = (group_id << 3) + (pid & 7);
    const int pid_n = (pid & 255) >> 3;
    const int bm = pid_m * BM;
    const int bn = pid_n * BN;

    // ---- global load mapping: 2 threads per 128B row, 4x16B chunks each ----
    const int r = tid >> 1;          // 0..127 row within tile
    const int h = tid & 1;           // 64B half
    const size_t aOff = (size_t)(bm + r) * K_DIM + h * 32;   // fp16 col offset
    const size_t bOff = (size_t)(bn + r) * K_DIM + h * 32;
    const uint32_t sRow = (uint32_t)(r * ROW_STRIDE + h * 64);

    // ---- ldmatrix lane bases ----
    const uint32_t aLane = sb +
        (uint32_t)((warpM * 32 + (lane & 15)) * ROW_STRIDE + ((lane >> 4) * 16));
    const uint32_t bLane = sb + TILE_BYTES +
        (uint32_t)((warpN * 64 + (lane & 7) + ((lane & 16) >> 1)) * ROW_STRIDE +
                   (((lane >> 3) & 1) * 16));

    float acc[2][8][4];
    #pragma unroll
    for (int i = 0; i < 2; i++)
        #pragma unroll
        for (int j = 0; j < 8; j++)
            #pragma unroll
            for (int q = 0; q < 4; q++)
                acc[i][j][q] = 0.0f;

    // ---- prologue: issue stages 0..STAGES-2 ----
    #pragma unroll
    for (int s = 0; s < STAGES - 1; s++) {
        const int k0 = s * BK;
        const uint32_t st = sb + s * STAGE_BYTES;
        #pragma unroll
        for (int c = 0; c < 4; c++) {
            cp16(st + sRow + c * 16, X + aOff + k0 + c * 8);
            cp16(st + TILE_BYTES + sRow + c * 16, W + bOff + k0 + c * 8);
        }
        CP_COMMIT();
    }

    uint32_t bufC = 0;
    uint32_t bufL = (STAGES - 1) * STAGE_BYTES;

    // double-buffered fragments
    uint32_t ar[2][2][4];   // [buf][mt][reg]
    uint32_t br[2][4][4];   // [buf][npair][reg]

    // ---- main loop: 64 tiles, 4 k16-slices each ----
    #pragma unroll 1
    for (int s = 0; s < KTILES; s++) {
        CP_WAIT(STAGES - 2);
        __syncthreads();

        const int ls = s + STAGES - 1;
        if (ls < KTILES) {
            const int k0 = ls * BK;
            const uint32_t st = sb + bufL;
            #pragma unroll
            for (int c = 0; c < 4; c++) {
                cp16(st + sRow + c * 16, X + aOff + k0 + c * 8);
                cp16(st + TILE_BYTES + sRow + c * 16, W + bOff + k0 + c * 8);
            }
        }
        CP_COMMIT();

        // fragments for k-slice 0
        ldsm4(ar[0][0], aLane + bufC);
        ldsm4(ar[0][1], aLane + bufC + 16 * ROW_STRIDE);
        #pragma unroll
        for (int p = 0; p < 4; p++)
            ldsm4(br[0][p], bLane + bufC + p * (16 * ROW_STRIDE));

        #pragma unroll
        for (int ks = 0; ks < 4; ks++) {
            const int cur = ks & 1;
            const int nxt = cur ^ 1;
            if (ks < 3) {   // prefetch slice ks+1 while computing ks
                const uint32_t o = bufC + (ks + 1) * 32;
                ldsm4(ar[nxt][0], aLane + o);
                ldsm4(ar[nxt][1], aLane + o + 16 * ROW_STRIDE);
                #pragma unroll
                for (int p = 0; p < 4; p++)
                    ldsm4(br[nxt][p], bLane + o + p * (16 * ROW_STRIDE));
            }
            #pragma unroll
            for (int mt = 0; mt < 2; mt++)
                #pragma unroll
                for (int nt = 0; nt < 8; nt++)
                    mma16816(acc[mt][nt], ar[cur][mt],
                             br[cur][nt >> 1][(nt & 1) * 2],
                             br[cur][nt >> 1][(nt & 1) * 2 + 1]);
        }

        bufC += STAGE_BYTES; if (bufC == SMEM_TOTAL) bufC = 0;
        bufL += STAGE_BYTES; if (bufL == SMEM_TOTAL) bufL = 0;
    }

    // ---- epilogue: direct stores + bias ----
    const int g = lane >> 2;
    const int t = lane & 3;
    #pragma unroll
    for (int mt = 0; mt < 2; mt++) {
        const int row0 = bm + warpM * 32 + mt * 16 + g;
        #pragma unroll
        for (int nt = 0; nt < 8; nt++) {
            const int col = bn + warpN * 64 + nt * 8 + 2 * t;
            const float2 b2 = *(const float2*)(bias + col);
            float2 o0, o1;
            o0.x = acc[mt][nt][0] + b2.x;
            o0.y = acc[mt][nt][1] + b2.y;
            o1.x = acc[mt][nt][2] + b2.x;
            o1.y = acc[mt][nt][3] + b2.y;
            *(float2*)(out + (size_t)row0 * N_DIM + col)       = o0;
            *(float2*)(out + (size_t)(row0 + 8) * N_DIM + col) = o1;
        }
    }
}

// ---------------- host ----------------
extern "C" void kernel_launch(void* const* d_in, const int* in_sizes, int n_in,
                              void* d_out, int out_size)
{
    const float* x    = (const float*)d_in[0];   // [M, K]
    const float* wr   = (const float*)d_in[1];   // [N, K]
    // d_in[2] = weight_imag: algebraically dead
    const float* bias = (const float*)d_in[3];   // [N]
    float* out = (float*)d_out;

    void *p_xh, *p_wh;
    cudaGetSymbolAddress(&p_xh, g_xh);
    cudaGetSymbolAddress(&p_wh, g_wh);

    to_fp16_fused<<<(N4X + N4W) / 256, 256>>>(
        (const float4*)x, (__half2*)p_xh,
        (const float4*)wr, (__half2*)p_wh);

    cudaFuncSetAttribute(qgemm_fp16, cudaFuncAttributeMaxDynamicSharedMemorySize,
                         SMEM_TOTAL);

    const int nblocks = (M_DIM / BM) * (N_DIM / BN);   // 2048
    qgemm_fp16<<<nblocks, 256, SMEM_TOTAL>>>(
        (const __half*)p_xh, (const __half*)p_wh, bias, out);
}

// round 9
// speedup vs baseline: 1.2612x; 1.2612x over previous
#include <cuda_runtime.h>
#include <cuda_fp16.h>
#include <cstdint>

// QuantumLinear == x @ W_real^T + bias  (magnitude*cos(atan2(i,r)) == r identically;
// weight_imag is dead code).
//
// Round 9: revert to the proven R7 GEMM config (BK=32, 4-stage, 80B stride,
// 2 CTAs/SM — 784us GEMM, at the fallback-HMMA per-instruction pacing floor),
// keep R8's fused single-launch fp32->fp16 prep.

#define M_DIM 8192
#define N_DIM 4096
#define K_DIM 4096

#define BM 128
#define BN 128
#define BK 32                       // fp16 elements per K-tile (64B rows)
#define STAGES 4
#define KTILES (K_DIM / BK)         // 128

// smem rows: 64B data + 16B pad = 80B stride -> conflict-free ldmatrix
#define ROW_STRIDE 80
#define TILE_BYTES (128 * ROW_STRIDE)          // 10240
#define STAGE_BYTES (2 * TILE_BYTES)           // 20480
#define SMEM_TOTAL (STAGES * STAGE_BYTES)      // 81920

// ---------------- scratch: fp16 copies ----------------
__device__ __half g_xh[(size_t)M_DIM * K_DIM];
__device__ __half g_wh[(size_t)N_DIM * K_DIM];

// ---------------- helpers ----------------
__device__ __forceinline__ uint32_t smem_u32(const void* p) {
    uint32_t a;
    asm("{ .reg .u64 t; cvta.to.shared.u64 t, %1; cvt.u32.u64 %0, t; }" : "=r"(a) : "l"(p));
    return a;
}

__device__ __forceinline__ void cp16(uint32_t dst, const void* src) {
    asm volatile("cp.async.cg.shared.global [%0], [%1], 16;" :: "r"(dst), "l"(src));
}
#define CP_COMMIT() asm volatile("cp.async.commit_group;" ::: "memory")
#define CP_WAIT(n)  asm volatile("cp.async.wait_group %0;" :: "n"(n) : "memory")

__device__ __forceinline__ void ldsm4(uint32_t* r, uint32_t addr) {
    asm volatile("ldmatrix.sync.aligned.m8n8.x4.shared.b16 {%0,%1,%2,%3}, [%4];"
                 : "=r"(r[0]), "=r"(r[1]), "=r"(r[2]), "=r"(r[3]) : "r"(addr));
}

__device__ __forceinline__ void mma16816(float* d, const uint32_t* a,
                                         uint32_t b0, uint32_t b1) {
    asm volatile(
        "mma.sync.aligned.m16n8k16.row.col.f32.f16.f16.f32 "
        "{%0,%1,%2,%3}, {%4,%5,%6,%7}, {%8,%9}, {%0,%1,%2,%3};"
        : "+f"(d[0]), "+f"(d[1]), "+f"(d[2]), "+f"(d[3])
        : "r"(a[0]), "r"(a[1]), "r"(a[2]), "r"(a[3]), "r"(b0), "r"(b1));
}

// ---------------- prep: fused fp32 -> fp16 (rn) for X then W ----------------
#define N4X (M_DIM * K_DIM / 4)    // 8388608
#define N4W (N_DIM * K_DIM / 4)    // 4194304

__global__ __launch_bounds__(256)
void to_fp16_fused(const float4* __restrict__ xs, __half2* __restrict__ xd,
                   const float4* __restrict__ ws, __half2* __restrict__ wd)
{
    int i = blockIdx.x * blockDim.x + threadIdx.x;
    const float4* s;
    __half2* d;
    if (i < N4X) { s = xs + i; d = xd + 2 * (size_t)i; }
    else         { int j = i - N4X; s = ws + j; d = wd + 2 * (size_t)j; }
    float4 v = *s;
    d[0] = __floats2half2_rn(v.x, v.y);
    d[1] = __floats2half2_rn(v.z, v.w);
}

// ---------------- GEMM (identical to Round 7) ----------------
__global__ __launch_bounds__(256, 2)
void qgemm_fp16(const __half* __restrict__ X,   // [M, K] fp16
                const __half* __restrict__ W,   // [N, K] fp16
                const float* __restrict__ bias, // [N]
                float* __restrict__ out)        // [M, N]
{
    extern __shared__ char smem[];
    const uint32_t sb = smem_u32(smem);

    const int tid  = threadIdx.x;
    const int wid  = tid >> 5;
    const int lane = tid & 31;
    const int warpM = wid & 3;      // m offset 32*warpM
    const int warpN = wid >> 2;     // n offset 64*warpN

    // ---- grouped rasterization: 8 m-tiles per group column ----
    const int pid = blockIdx.x;
    const int group_id = pid >> 8;
    const int pid_m = (group_id << 3) + (pid & 7);
    const int pid_n = (pid & 255) >> 3;
    const int bm = pid_m * BM;
    const int bn = pid_n * BN;

    // ---- global load mapping: 2 rows per thread per tile, 16B chunks ----
    const int ldr   = tid >> 2;       // 0..63
    const int chunk = tid & 3;        // 0..3 (16B = 8 halves)
    const size_t aOff0 = (size_t)(bm + ldr) * K_DIM + chunk * 8;
    const size_t aOff1 = aOff0 + (size_t)64 * K_DIM;
    const size_t bOff0 = (size_t)(bn + ldr) * K_DIM + chunk * 8;
    const size_t bOff1 = bOff0 + (size_t)64 * K_DIM;
    const uint32_t sA0 = ldr * ROW_STRIDE + chunk * 16;
    const uint32_t sA1 = sA0 + 64 * ROW_STRIDE;

    // ---- ldmatrix lane bases ----
    const uint32_t aLane = sb +
        (uint32_t)((warpM * 32 + (lane & 15)) * ROW_STRIDE + ((lane >> 4) * 16));
    const uint32_t bLane = sb + TILE_BYTES +
        (uint32_t)((warpN * 64 + (lane & 7) + ((lane & 16) >> 1)) * ROW_STRIDE +
                   (((lane >> 3) & 1) * 16));

    float acc[2][8][4];
    #pragma unroll
    for (int i = 0; i < 2; i++)
        #pragma unroll
        for (int j = 0; j < 8; j++)
            #pragma unroll
            for (int q = 0; q < 4; q++)
                acc[i][j][q] = 0.0f;

    // ---- prologue: issue stages 0..STAGES-2 ----
    #pragma unroll
    for (int s = 0; s < STAGES - 1; s++) {
        const int k0 = s * BK;
        const uint32_t st = sb + s * STAGE_BYTES;
        cp16(st + sA0, X + aOff0 + k0);
        cp16(st + sA1, X + aOff1 + k0);
        cp16(st + TILE_BYTES + sA0, W + bOff0 + k0);
        cp16(st + TILE_BYTES + sA1, W + bOff1 + k0);
        CP_COMMIT();
    }

    uint32_t bufC = 0;
    uint32_t bufL = (STAGES - 1) * STAGE_BYTES;

    // double-buffered fragments
    uint32_t ar[2][2][4];   // [buf][mt][reg]
    uint32_t br[2][4][4];   // [buf][npair][reg]

    // ---- main loop ----
    #pragma unroll 1
    for (int s = 0; s < KTILES; s++) {
        CP_WAIT(STAGES - 2);
        __syncthreads();

        const int ls = s + STAGES - 1;
        if (ls < KTILES) {
            const int k0 = ls * BK;
            const uint32_t st = sb + bufL;
            cp16(st + sA0, X + aOff0 + k0);
            cp16(st + sA1, X + aOff1 + k0);
            cp16(st + TILE_BYTES + sA0, W + bOff0 + k0);
            cp16(st + TILE_BYTES + sA1, W + bOff1 + k0);
        }
        CP_COMMIT();

        // fragments for k-slice 0
        ldsm4(ar[0][0], aLane + bufC);
        ldsm4(ar[0][1], aLane + bufC + 16 * ROW_STRIDE);
        #pragma unroll
        for (int p = 0; p < 4; p++)
            ldsm4(br[0][p], bLane + bufC + p * (16 * ROW_STRIDE));

        #pragma unroll
        for (int ks = 0; ks < 2; ks++) {
            const int cur = ks & 1;
            const int nxt = cur ^ 1;
            if (ks < 1) {   // prefetch slice 1 while computing slice 0
                const uint32_t o = bufC + 32;
                ldsm4(ar[nxt][0], aLane + o);
                ldsm4(ar[nxt][1], aLane + o + 16 * ROW_STRIDE);
                #pragma unroll
                for (int p = 0; p < 4; p++)
                    ldsm4(br[nxt][p], bLane + o + p * (16 * ROW_STRIDE));
            }
            #pragma unroll
            for (int mt = 0; mt < 2; mt++)
                #pragma unroll
                for (int nt = 0; nt < 8; nt++)
                    mma16816(acc[mt][nt], ar[cur][mt],
                             br[cur][nt >> 1][(nt & 1) * 2],
                             br[cur][nt >> 1][(nt & 1) * 2 + 1]);
        }

        bufC += STAGE_BYTES; if (bufC == SMEM_TOTAL) bufC = 0;
        bufL += STAGE_BYTES; if (bufL == SMEM_TOTAL) bufL = 0;
    }

    // ---- epilogue: direct stores + bias ----
    const int g = lane >> 2;
    const int t = lane & 3;
    #pragma unroll
    for (int mt = 0; mt < 2; mt++) {
        const int row0 = bm + warpM * 32 + mt * 16 + g;
        #pragma unroll
        for (int nt = 0; nt < 8; nt++) {
            const int col = bn + warpN * 64 + nt * 8 + 2 * t;
            const float2 b2 = *(const float2*)(bias + col);
            float2 o0, o1;
            o0.x = acc[mt][nt][0] + b2.x;
            o0.y = acc[mt][nt][1] + b2.y;
            o1.x = acc[mt][nt][2] + b2.x;
            o1.y = acc[mt][nt][3] + b2.y;
            *(float2*)(out + (size_t)row0 * N_DIM + col)       = o0;
            *(float2*)(out + (size_t)(row0 + 8) * N_DIM + col) = o1;
        }
    }
}

// ---------------- host ----------------
extern "C" void kernel_launch(void* const* d_in, const int* in_sizes, int n_in,
                              void* d_out, int out_size)
{
    const float* x    = (const float*)d_in[0];   // [M, K]
    const float* wr   = (const float*)d_in[1];   // [N, K]
    // d_in[2] = weight_imag: algebraically dead
    const float* bias = (const float*)d_in[3];   // [N]
    float* out = (float*)d_out;

    void *p_xh, *p_wh;
    cudaGetSymbolAddress(&p_xh, g_xh);
    cudaGetSymbolAddress(&p_wh, g_wh);

    to_fp16_fused<<<(N4X + N4W) / 256, 256>>>(
        (const float4*)x, (__half2*)p_xh,
        (const float4*)wr, (__half2*)p_wh);

    cudaFuncSetAttribute(qgemm_fp16, cudaFuncAttributeMaxDynamicSharedMemorySize,
                         SMEM_TOTAL);

    const int nblocks = (M_DIM / BM) * (N_DIM / BN);   // 2048
    qgemm_fp16<<<nblocks, 256, SMEM_TOTAL>>>(
        (const __half*)p_xh, (const __half*)p_wh, bias, out);
}

// round 10
// speedup vs baseline: 1.4118x; 1.1193x over previous
#include <cuda_runtime.h>
#include <cuda_fp16.h>
#include <cstdint>

// QuantumLinear == x @ W_real^T + bias  (magnitude*cos(atan2(i,r)) == r identically;
// weight_imag is dead code).
//
// Round 10: fp16 m16n8k16 single pass. Tensor-busy time is ~453us but GEMM ran
// 784us (tensor=58%) -> issue stalls. Fix: software-pipeline ldmatrix ACROSS the
// tile barrier. With 5 stages and CP_WAIT(2) before the barrier, stage s+1 data
// is globally visible during iter s, so we preload its slice-0 fragments at the
// end of iter s -> no exposed LDSM latency after any __syncthreads.

#define M_DIM 8192
#define N_DIM 4096
#define K_DIM 4096

#define BM 128
#define BN 128
#define BK 32                       // fp16 elements per K-tile (64B rows)
#define STAGES 5
#define KTILES (K_DIM / BK)         // 128

// smem rows: 64B data + 16B pad = 80B stride -> conflict-free ldmatrix
#define ROW_STRIDE 80
#define TILE_BYTES (128 * ROW_STRIDE)          // 10240
#define STAGE_BYTES (2 * TILE_BYTES)           // 20480
#define SMEM_TOTAL (STAGES * STAGE_BYTES)      // 102400 (x2 CTAs = 200KB/SM)

// ---------------- scratch: fp16 copies ----------------
__device__ __half g_xh[(size_t)M_DIM * K_DIM];
__device__ __half g_wh[(size_t)N_DIM * K_DIM];

// ---------------- helpers ----------------
__device__ __forceinline__ uint32_t smem_u32(const void* p) {
    uint32_t a;
    asm("{ .reg .u64 t; cvta.to.shared.u64 t, %1; cvt.u32.u64 %0, t; }" : "=r"(a) : "l"(p));
    return a;
}

__device__ __forceinline__ void cp16(uint32_t dst, const void* src) {
    asm volatile("cp.async.cg.shared.global [%0], [%1], 16;" :: "r"(dst), "l"(src));
}
#define CP_COMMIT() asm volatile("cp.async.commit_group;" ::: "memory")
#define CP_WAIT(n)  asm volatile("cp.async.wait_group %0;" :: "n"(n) : "memory")

__device__ __forceinline__ void ldsm4(uint32_t* r, uint32_t addr) {
    asm volatile("ldmatrix.sync.aligned.m8n8.x4.shared.b16 {%0,%1,%2,%3}, [%4];"
                 : "=r"(r[0]), "=r"(r[1]), "=r"(r[2]), "=r"(r[3]) : "r"(addr));
}

__device__ __forceinline__ void mma16816(float* d, const uint32_t* a,
                                         uint32_t b0, uint32_t b1) {
    asm volatile(
        "mma.sync.aligned.m16n8k16.row.col.f32.f16.f16.f32 "
        "{%0,%1,%2,%3}, {%4,%5,%6,%7}, {%8,%9}, {%0,%1,%2,%3};"
        : "+f"(d[0]), "+f"(d[1]), "+f"(d[2]), "+f"(d[3])
        : "r"(a[0]), "r"(a[1]), "r"(a[2]), "r"(a[3]), "r"(b0), "r"(b1));
}

// ---------------- prep: fused fp32 -> fp16 (rn) for X then W ----------------
#define N4X (M_DIM * K_DIM / 4)    // 8388608
#define N4W (N_DIM * K_DIM / 4)    // 4194304

__global__ __launch_bounds__(256)
void to_fp16_fused(const float4* __restrict__ xs, __half2* __restrict__ xd,
                   const float4* __restrict__ ws, __half2* __restrict__ wd)
{
    int i = blockIdx.x * blockDim.x + threadIdx.x;
    const float4* s;
    __half2* d;
    if (i < N4X) { s = xs + i; d = xd + 2 * (size_t)i; }
    else         { int j = i - N4X; s = ws + j; d = wd + 2 * (size_t)j; }
    float4 v = *s;
    d[0] = __floats2half2_rn(v.x, v.y);
    d[1] = __floats2half2_rn(v.z, v.w);
}

// ---------------- GEMM ----------------
__global__ __launch_bounds__(256, 2)
void qgemm_fp16(const __half* __restrict__ X,   // [M, K] fp16
                const __half* __restrict__ W,   // [N, K] fp16
                const float* __restrict__ bias, // [N]
                float* __restrict__ out)        // [M, N]
{
    extern __shared__ char smem[];
    const uint32_t sb = smem_u32(smem);

    const int tid  = threadIdx.x;
    const int wid  = tid >> 5;
    const int lane = tid & 31;
    const int warpM = wid & 3;      // m offset 32*warpM
    const int warpN = wid >> 2;     // n offset 64*warpN

    // ---- grouped rasterization: 8 m-tiles per group column ----
    const int pid = blockIdx.x;
    const int group_id = pid >> 8;
    const int pid_m = (group_id << 3) + (pid & 7);
    const int pid_n = (pid & 255) >> 3;
    const int bm = pid_m * BM;
    const int bn = pid_n * BN;

    // ---- global load mapping: 2 rows per thread per tile, 16B chunks ----
    const int ldr   = tid >> 2;       // 0..63
    const int chunk = tid & 3;        // 0..3 (16B = 8 halves)
    const size_t aOff0 = (size_t)(bm + ldr) * K_DIM + chunk * 8;
    const size_t aOff1 = aOff0 + (size_t)64 * K_DIM;
    const size_t bOff0 = (size_t)(bn + ldr) * K_DIM + chunk * 8;
    const size_t bOff1 = bOff0 + (size_t)64 * K_DIM;
    const uint32_t sA0 = ldr * ROW_STRIDE + chunk * 16;
    const uint32_t sA1 = sA0 + 64 * ROW_STRIDE;

    // ---- ldmatrix lane bases ----
    const uint32_t aLane = sb +
        (uint32_t)((warpM * 32 + (lane & 15)) * ROW_STRIDE + ((lane >> 4) * 16));
    const uint32_t bLane = sb + TILE_BYTES +
        (uint32_t)((warpN * 64 + (lane & 7) + ((lane & 16) >> 1)) * ROW_STRIDE +
                   (((lane >> 3) & 1) * 16));

    float acc[2][8][4];
    #pragma unroll
    for (int i = 0; i < 2; i++)
        #pragma unroll
        for (int j = 0; j < 8; j++)
            #pragma unroll
            for (int q = 0; q < 4; q++)
                acc[i][j][q] = 0.0f;

    // ---- prologue: issue stages 0..STAGES-2 (4 groups) ----
    #pragma unroll
    for (int s = 0; s < STAGES - 1; s++) {
        const int k0 = s * BK;
        const uint32_t st = sb + s * STAGE_BYTES;
        cp16(st + sA0, X + aOff0 + k0);
        cp16(st + sA1, X + aOff1 + k0);
        cp16(st + TILE_BYTES + sA0, W + bOff0 + k0);
        cp16(st + TILE_BYTES + sA1, W + bOff1 + k0);
        CP_COMMIT();
    }

    uint32_t bufC = 0;
    uint32_t bufL = (STAGES - 1) * STAGE_BYTES;

    // fragment buffers: [0]=slice0, [1]=slice1 (fixed roles)
    uint32_t ar[2][2][4];   // [slice][mt][reg]
    uint32_t br[2][4][4];   // [slice][npair][reg]

    // ---- preload slice0 fragments of stage 0 ----
    CP_WAIT(3);            // stage 0 arrived (own thread)
    __syncthreads();       // visible to all
    ldsm4(ar[0][0], aLane + bufC);
    ldsm4(ar[0][1], aLane + bufC + 16 * ROW_STRIDE);
    #pragma unroll
    for (int p = 0; p < 4; p++)
        ldsm4(br[0][p], bLane + bufC + p * (16 * ROW_STRIDE));

    // ---- main loop (cross-barrier fragment pipeline) ----
    #pragma unroll 1
    for (int s = 0; s < KTILES; s++) {
        // groups committed so far: 4 + s; all but 2 done -> stages 0..s+1 ready
        CP_WAIT(2);
        __syncthreads();   // stage s+1 now globally visible; buffer (s-1)%5 free

        // issue cp for stage s+4 into buffer (s-1)%5
        const int ls = s + STAGES - 1;
        if (ls < KTILES) {
            const int k0 = ls * BK;
            const uint32_t st = sb + bufL;
            cp16(st + sA0, X + aOff0 + k0);
            cp16(st + sA1, X + aOff1 + k0);
            cp16(st + TILE_BYTES + sA0, W + bOff0 + k0);
            cp16(st + TILE_BYTES + sA1, W + bOff1 + k0);
        }
        CP_COMMIT();

        // prefetch slice1 of stage s
        {
            const uint32_t o = bufC + 32;
            ldsm4(ar[1][0], aLane + o);
            ldsm4(ar[1][1], aLane + o + 16 * ROW_STRIDE);
            #pragma unroll
            for (int p = 0; p < 4; p++)
                ldsm4(br[1][p], bLane + o + p * (16 * ROW_STRIDE));
        }

        // mma slice0 (fragments preloaded last iteration)
        #pragma unroll
        for (int mt = 0; mt < 2; mt++)
            #pragma unroll
            for (int nt = 0; nt < 8; nt++)
                mma16816(acc[mt][nt], ar[0][mt],
                         br[0][nt >> 1][(nt & 1) * 2],
                         br[0][nt >> 1][(nt & 1) * 2 + 1]);

        // prefetch slice0 of stage s+1 (data visible since this iter's barrier;
        // its buffer is not rewritten until iter s+2 -> safe)
        uint32_t bufN = bufC + STAGE_BYTES;
        if (bufN == SMEM_TOTAL) bufN = 0;
        if (s + 1 < KTILES) {
            ldsm4(ar[0][0], aLane + bufN);
            ldsm4(ar[0][1], aLane + bufN + 16 * ROW_STRIDE);
            #pragma unroll
            for (int p = 0; p < 4; p++)
                ldsm4(br[0][p], bLane + bufN + p * (16 * ROW_STRIDE));
        }

        // mma slice1
        #pragma unroll
        for (int mt = 0; mt < 2; mt++)
            #pragma unroll
            for (int nt = 0; nt < 8; nt++)
                mma16816(acc[mt][nt], ar[1][mt],
                         br[1][nt >> 1][(nt & 1) * 2],
                         br[1][nt >> 1][(nt & 1) * 2 + 1]);

        bufC = bufN;
        bufL += STAGE_BYTES; if (bufL == SMEM_TOTAL) bufL = 0;
    }

    // ---- epilogue: direct stores + bias ----
    const int g = lane >> 2;
    const int t = lane & 3;
    #pragma unroll
    for (int mt = 0; mt < 2; mt++) {
        const int row0 = bm + warpM * 32 + mt * 16 + g;
        #pragma unroll
        for (int nt = 0; nt < 8; nt++) {
            const int col = bn + warpN * 64 + nt * 8 + 2 * t;
            const float2 b2 = *(const float2*)(bias + col);
            float2 o0, o1;
            o0.x = acc[mt][nt][0] + b2.x;
            o0.y = acc[mt][nt][1] + b2.y;
            o1.x = acc[mt][nt][2] + b2.x;
            o1.y = acc[mt][nt][3] + b2.y;
            *(float2*)(out + (size_t)row0 * N_DIM + col)       = o0;
            *(float2*)(out + (size_t)(row0 + 8) * N_DIM + col) = o1;
        }
    }
}

// ---------------- host ----------------
extern "C" void kernel_launch(void* const* d_in, const int* in_sizes, int n_in,
                              void* d_out, int out_size)
{
    const float* x    = (const float*)d_in[0];   // [M, K]
    const float* wr   = (const float*)d_in[1];   // [N, K]
    // d_in[2] = weight_imag: algebraically dead
    const float* bias = (const float*)d_in[3];   // [N]
    float* out = (float*)d_out;

    void *p_xh, *p_wh;
    cudaGetSymbolAddress(&p_xh, g_xh);
    cudaGetSymbolAddress(&p_wh, g_wh);

    to_fp16_fused<<<(N4X + N4W) / 256, 256>>>(
        (const float4*)x, (__half2*)p_xh,
        (const float4*)wr, (__half2*)p_wh);

    cudaFuncSetAttribute(qgemm_fp16, cudaFuncAttributeMaxDynamicSharedMemorySize,
                         SMEM_TOTAL);

    const int nblocks = (M_DIM / BM) * (N_DIM / BN);   // 2048
    qgemm_fp16<<<nblocks, 256, SMEM_TOTAL>>>(
        (const __half*)p_xh, (const __half*)p_wh, bias, out);
}